// round 17
// baseline (speedup 1.0000x reference)
#include <cuda_runtime.h>
#include <cuda_fp16.h>
#include <cstdint>
#include <math.h>

// Problem constants
#define DIMC 1024
#define HC   16
#define DHC  64
#define BC   4
#define LC   4096
#define RC   512
#define SCALEF 0.125f   // 64^-0.5

// ---------------------------------------------------------------------------
// Device-global scratch (all activations fp16)
// ---------------------------------------------------------------------------
__device__ __half g_Qh [(size_t)BC * LC * DIMC];
__device__ __half g_Kh [(size_t)BC * RC * DIMC];
__device__ __half g_Vh [(size_t)BC * RC * DIMC];
__device__ __half g_Oh [(size_t)BC * LC * DIMC];
__device__ __half g_Xr [(size_t)BC * LC * DIMC];
__device__ __half g_Cr [(size_t)BC * RC * DIMC];
__device__ __half g_WqT [(size_t)DIMC * DIMC];
__device__ __half g_WkvT[(size_t)2 * DIMC * DIMC];
__device__ __half g_WoT [(size_t)DIMC * DIMC];

// ---------------------------------------------------------------------------
// Helpers
// ---------------------------------------------------------------------------
__device__ __forceinline__ uint32_t smem_u32(const void* p) {
    uint32_t a;
    asm("{ .reg .u64 t; cvta.to.shared.u64 t, %1; cvt.u32.u64 %0, t; }" : "=r"(a) : "l"(p));
    return a;
}

#define CP_ASYNC16(dst, src) \
    asm volatile("cp.async.cg.shared.global [%0], [%1], 16;" :: "r"(dst), "l"(src) : "memory")
#define CP_COMMIT() asm volatile("cp.async.commit_group;" ::: "memory")
#define CP_WAIT(n)  asm volatile("cp.async.wait_group %0;" :: "n"(n) : "memory")

__device__ __forceinline__ void mma_f16(float* c, const uint32_t* a, const uint32_t* b) {
    asm volatile(
        "mma.sync.aligned.m16n8k16.row.col.f32.f16.f16.f32 "
        "{%0,%1,%2,%3}, {%4,%5,%6,%7}, {%8,%9}, {%0,%1,%2,%3};"
        : "+f"(c[0]), "+f"(c[1]), "+f"(c[2]), "+f"(c[3])
        : "r"(a[0]), "r"(a[1]), "r"(a[2]), "r"(a[3]), "r"(b[0]), "r"(b[1]));
}

__device__ __forceinline__ void ldmx4(uint32_t& r0, uint32_t& r1, uint32_t& r2, uint32_t& r3,
                                      uint32_t addr) {
    asm volatile("ldmatrix.sync.aligned.m8n8.x4.shared.b16 {%0,%1,%2,%3}, [%4];"
                 : "=r"(r0), "=r"(r1), "=r"(r2), "=r"(r3) : "r"(addr));
}
__device__ __forceinline__ void ldmx4t(uint32_t& r0, uint32_t& r1, uint32_t& r2, uint32_t& r3,
                                       uint32_t addr) {
    asm volatile("ldmatrix.sync.aligned.m8n8.x4.trans.shared.b16 {%0,%1,%2,%3}, [%4];"
                 : "=r"(r0), "=r"(r1), "=r"(r2), "=r"(r3) : "r"(addr));
}
__device__ __forceinline__ uint32_t h2u(float a, float b) {
    __half2 h = __floats2half2_rn(a, b);
    return *(uint32_t*)&h;
}

// ---------------------------------------------------------------------------
// Preprocessing kernels (fp32 -> fp16)
// ---------------------------------------------------------------------------
__global__ __launch_bounds__(256) void round_copy_h_kernel(const float* __restrict__ src,
                                                           __half* __restrict__ dst, int n4) {
    int i = blockIdx.x * 256 + threadIdx.x;
    if (i < n4) {
        float4 v = ((const float4*)src)[i];
        ((__half2*)dst)[2 * i]     = __floats2half2_rn(v.x, v.y);
        ((__half2*)dst)[2 * i + 1] = __floats2half2_rn(v.z, v.w);
    }
}

__global__ __launch_bounds__(256) void transpose_all_kernel(const float* __restrict__ W0,
                                                            const float* __restrict__ W1,
                                                            const float* __restrict__ W2,
                                                            const float* __restrict__ W3,
                                                            __half* __restrict__ T0,
                                                            __half* __restrict__ T1,
                                                            __half* __restrict__ T2,
                                                            __half* __restrict__ T3) {
    __shared__ float t[32][33];
    const float* W;
    __half* Wt;
    float scale = 1.0f;
    switch (blockIdx.z) {
        case 0: W = W0; Wt = T0; scale = SCALEF; break;
        case 1: W = W1; Wt = T1; break;
        case 2: W = W2; Wt = T2; break;
        default: W = W3; Wt = T3; break;
    }
    int tx = threadIdx.x & 31;
    int ty = threadIdx.x >> 5;
    int x = blockIdx.x * 32 + tx;
#pragma unroll
    for (int i = ty; i < 32; i += 8) {
        int y = blockIdx.y * 32 + i;
        t[i][tx] = W[(size_t)y * DIMC + x] * scale;
    }
    __syncthreads();
    int xo = blockIdx.y * 32 + tx;
#pragma unroll
    for (int i = ty; i < 32; i += 8) {
        int yo = blockIdx.x * 32 + i;
        Wt[(size_t)yo * DIMC + xo] = __float2half_rn(t[tx][i]);
    }
}

// ---------------------------------------------------------------------------
// fp16 mma.sync GEMM v3: CTA tile 128x256, warp tile 64x64 (8 warps = 2m x 4n),
// BK=64 halfs, swizzled 128B rows, 4-stage cp.async, 1 CTA/SM (256 regs).
// half_out=1 -> fp16 store; 0 -> fp32 store. Column-split output (KV fusion).
// ---------------------------------------------------------------------------
#define BKH 64
#define BMv 128
#define BNv 256
#define A_BYTES (128 * 128)          // 16 KB
#define B_BYTES (256 * 128)          // 32 KB
#define STGv (A_BYTES + B_BYTES)     // 48 KB
#define NSTG 4
#define GSM_TOTAL (NSTG * STGv)      // 196608 B

__device__ __forceinline__ void load_stage(uint32_t sbase, const __half* __restrict__ Ab,
                                           const __half* __restrict__ Bb, int kt, int tid) {
    uint32_t sA = sbase;
    uint32_t sB = sbase + A_BYTES;
    const __half* As_ = Ab + kt * BKH;
    const __half* Bs_ = Bb + kt * BKH;
#pragma unroll
    for (int i = 0; i < 4; i++) {        // A: 128 rows x 8 granules
        int id = tid + i * 256;
        int r = id >> 3;
        int gr = id & 7;
        CP_ASYNC16(sA + (uint32_t)(r * 128 + ((gr ^ (r & 7)) << 4)),
                   As_ + (size_t)r * DIMC + gr * 8);
    }
#pragma unroll
    for (int i = 0; i < 8; i++) {        // B: 256 rows x 8 granules
        int id = tid + i * 256;
        int r = id >> 3;
        int gr = id & 7;
        CP_ASYNC16(sB + (uint32_t)(r * 128 + ((gr ^ (r & 7)) << 4)),
                   Bs_ + (size_t)r * DIMC + gr * 8);
    }
}

__global__ __launch_bounds__(256, 1) void mma_gemm_kernel(const __half* __restrict__ A,
                                                          const __half* __restrict__ Bt,
                                                          void* __restrict__ C,
                                                          void* __restrict__ C2,
                                                          int nsplit,
                                                          int half_out) {
    extern __shared__ float sm[];
    const int tid = threadIdx.x;
    const int lane = tid & 31;
    const int g = lane >> 2;
    const int tg = lane & 3;
    const int wid = tid >> 5;
    const int wm = (wid & 1) * 64;       // 2 warps along M
    const int wn = (wid >> 1) * 64;      // 4 warps along N

    const int a_row = (lane & 7) + ((lane >> 3) & 1) * 8;
    const int a_g   = lane >> 4;
    const int b_row = (lane & 7) + (lane >> 4) * 8;
    const int b_g   = (lane >> 3) & 1;

    const __half* Ab = A  + (size_t)blockIdx.y * BMv * DIMC;
    const __half* Bb = Bt + (size_t)blockIdx.x * BNv * DIMC;
    uint32_t sb = smem_u32(sm);

    uint32_t aBase[4], bBase[4];
    int aX[4], bX[4];
#pragma unroll
    for (int mi = 0; mi < 4; mi++) {
        int R = wm + a_row + mi * 16;
        aBase[mi] = (uint32_t)(R * 128);
        aX[mi] = R & 7;
    }
#pragma unroll
    for (int j = 0; j < 4; j++) {
        int R = wn + b_row + j * 16;
        bBase[j] = (uint32_t)(A_BYTES + R * 128);
        bX[j] = R & 7;
    }

    float acc[4][8][4];
#pragma unroll
    for (int mi = 0; mi < 4; mi++)
#pragma unroll
        for (int nj = 0; nj < 8; nj++)
#pragma unroll
            for (int q = 0; q < 4; q++) acc[mi][nj][q] = 0.f;

    load_stage(sb + 0 * STGv, Ab, Bb, 0, tid); CP_COMMIT();
    load_stage(sb + 1 * STGv, Ab, Bb, 1, tid); CP_COMMIT();
    load_stage(sb + 2 * STGv, Ab, Bb, 2, tid); CP_COMMIT();

    const int NKT = DIMC / BKH;   // 16
    for (int kt = 0; kt < NKT; kt++) {
        if (kt < NKT - 2)      { CP_WAIT(2); }
        else if (kt == NKT - 2){ CP_WAIT(1); }
        else                   { CP_WAIT(0); }
        __syncthreads();

        uint32_t stg = sb + (uint32_t)((kt % NSTG) * STGv);

#pragma unroll
        for (int kk = 0; kk < BKH; kk += 16) {
            int Ga = (kk >> 3) + a_g;
            int Gb = (kk >> 3) + b_g;
            uint32_t a[4][4], b[8][2];
#pragma unroll
            for (int mi = 0; mi < 4; mi++)
                ldmx4(a[mi][0], a[mi][1], a[mi][2], a[mi][3],
                      stg + aBase[mi] + (uint32_t)((Ga ^ aX[mi]) << 4));
#pragma unroll
            for (int j = 0; j < 4; j++)
                ldmx4(b[2 * j][0], b[2 * j][1], b[2 * j + 1][0], b[2 * j + 1][1],
                      stg + bBase[j] + (uint32_t)((Gb ^ bX[j]) << 4));
#pragma unroll
            for (int mi = 0; mi < 4; mi++)
#pragma unroll
                for (int nj = 0; nj < 8; nj++)
                    mma_f16(acc[mi][nj], a[mi], b[nj]);
        }

        if (kt + 3 < NKT) {
            load_stage(sb + (uint32_t)(((kt + 3) % NSTG) * STGv), Ab, Bb, kt + 3, tid);
            CP_COMMIT();
        }
    }

    int colb = blockIdx.x * BNv;
    void* Cout = C;
    if (colb >= nsplit) { Cout = C2; colb -= nsplit; }
    size_t rowb = (size_t)blockIdx.y * BMv + wm + g;

    if (half_out) {
#pragma unroll
        for (int mi = 0; mi < 4; mi++) {
            __half* C0 = (__half*)Cout + (rowb + mi * 16) * DIMC + colb + wn;
            __half* C1 = C0 + 8 * DIMC;
#pragma unroll
            for (int nj = 0; nj < 8; nj++) {
                *(__half2*)(C0 + nj * 8 + tg * 2) = __floats2half2_rn(acc[mi][nj][0], acc[mi][nj][1]);
                *(__half2*)(C1 + nj * 8 + tg * 2) = __floats2half2_rn(acc[mi][nj][2], acc[mi][nj][3]);
            }
        }
    } else {
#pragma unroll
        for (int mi = 0; mi < 4; mi++) {
            float* C0 = (float*)Cout + (rowb + mi * 16) * DIMC + colb + wn;
            float* C1 = C0 + 8 * DIMC;
#pragma unroll
            for (int nj = 0; nj < 8; nj++) {
                *(float2*)(C0 + nj * 8 + tg * 2) = make_float2(acc[mi][nj][0], acc[mi][nj][1]);
                *(float2*)(C1 + nj * 8 + tg * 2) = make_float2(acc[mi][nj][2], acc[mi][nj][3]);
            }
        }
    }
}

// ---------------------------------------------------------------------------
// Flash attention (fp16 mma, register S/P, online softmax) — unchanged R16
// ---------------------------------------------------------------------------
#define AFL_SMEM 81920

__device__ __forceinline__ void attn_load_chunk(uint32_t dst, const __half* __restrict__ src,
                                                int tid) {
#pragma unroll
    for (int i = 0; i < 4; i++) {
        int id = tid + i * 256;
        int r = id >> 3;
        int gr = id & 7;
        CP_ASYNC16(dst + (uint32_t)(r * 128 + ((gr ^ (r & 7)) << 4)),
                   src + (size_t)r * DIMC + gr * 8);
    }
}

__global__ __launch_bounds__(256, 1) void attn_flash_kernel() {
    extern __shared__ char smc[];
    uint32_t sb = smem_u32(smc);

    const int tid = threadIdx.x;
    const int lane = tid & 31;
    const int g = lane >> 2;
    const int tg = lane & 3;
    const int wid = tid >> 5;
    const int wm = wid * 16;
    const int bh = blockIdx.y;
    const int b = bh >> 4;
    const int h = bh & 15;
    const int q0 = blockIdx.x * 128;

    const int a_row = (lane & 7) + ((lane >> 3) & 1) * 8;
    const int a_g   = lane >> 4;
    const int b_row = (lane & 7) + (lane >> 4) * 8;
    const int b_g   = (lane >> 3) & 1;

    const __half* Qg = g_Qh + ((size_t)(b * LC + q0)) * DIMC + h * DHC;
    const __half* Kg = g_Kh + ((size_t)(b * RC)) * DIMC + h * DHC;
    const __half* Vg = g_Vh + ((size_t)(b * RC)) * DIMC + h * DHC;

    attn_load_chunk(sb, Qg, tid);                 CP_COMMIT();
    attn_load_chunk(sb + 16384, Kg, tid);         CP_COMMIT();
    attn_load_chunk(sb + 32768, Vg, tid);         CP_COMMIT();

    CP_WAIT(2);
    __syncthreads();

    uint32_t qf[4][4];
    {
        int R = wm + a_row;
        uint32_t qbase = sb + (uint32_t)(R * 128);
        int x = R & 7;
#pragma unroll
        for (int k4 = 0; k4 < 4; k4++)
            ldmx4(qf[k4][0], qf[k4][1], qf[k4][2], qf[k4][3],
                  qbase + (uint32_t)(((2 * k4 + a_g) ^ x) << 4));
    }

    float o[8][4];
#pragma unroll
    for (int n = 0; n < 8; n++)
#pragma unroll
        for (int q = 0; q < 4; q++) o[n][q] = 0.f;
    float m0 = -1e30f, m1 = -1e30f, l0 = 0.f, l1 = 0.f;

    for (int c = 0; c < 4; c++) {
        CP_WAIT(1);
        __syncthreads();
        if (c < 3) {
            attn_load_chunk(sb + 16384 + (uint32_t)(((c + 1) & 1) * 32768),
                            Kg + (size_t)(c + 1) * 128 * DIMC, tid);
            CP_COMMIT();
            attn_load_chunk(sb + 32768 + (uint32_t)(((c + 1) & 1) * 32768),
                            Vg + (size_t)(c + 1) * 128 * DIMC, tid);
            CP_COMMIT();
        }
        uint32_t kbuf = sb + 16384 + (uint32_t)((c & 1) * 32768);

        float e[16][4];
#pragma unroll
        for (int n = 0; n < 16; n++)
#pragma unroll
            for (int q = 0; q < 4; q++) e[n][q] = 0.f;

#pragma unroll
        for (int k4 = 0; k4 < 4; k4++) {
            int Gb = 2 * k4 + b_g;
#pragma unroll
            for (int j = 0; j < 8; j++) {
                int R = 16 * j + b_row;
                uint32_t bb0, bb1, bb2, bb3;
                ldmx4(bb0, bb1, bb2, bb3,
                      kbuf + (uint32_t)(R * 128 + ((Gb ^ (R & 7)) << 4)));
                uint32_t bA[2] = {bb0, bb1}, bB[2] = {bb2, bb3};
                mma_f16(e[2 * j],     qf[k4], bA);
                mma_f16(e[2 * j + 1], qf[k4], bB);
            }
        }

        float rm0 = -1e30f, rm1 = -1e30f;
#pragma unroll
        for (int n = 0; n < 16; n++) {
            rm0 = fmaxf(rm0, fmaxf(e[n][0], e[n][1]));
            rm1 = fmaxf(rm1, fmaxf(e[n][2], e[n][3]));
        }
        rm0 = fmaxf(rm0, __shfl_xor_sync(0xffffffffu, rm0, 1));
        rm0 = fmaxf(rm0, __shfl_xor_sync(0xffffffffu, rm0, 2));
        rm1 = fmaxf(rm1, __shfl_xor_sync(0xffffffffu, rm1, 1));
        rm1 = fmaxf(rm1, __shfl_xor_sync(0xffffffffu, rm1, 2));

        float m0n = fmaxf(m0, rm0);
        float m1n = fmaxf(m1, rm1);
        float sc0 = __expf(m0 - m0n);
        float sc1 = __expf(m1 - m1n);
        m0 = m0n; m1 = m1n;

        float s0 = 0.f, s1 = 0.f;
#pragma unroll
        for (int n = 0; n < 16; n++) {
            e[n][0] = __expf(e[n][0] - m0);
            e[n][1] = __expf(e[n][1] - m0);
            e[n][2] = __expf(e[n][2] - m1);
            e[n][3] = __expf(e[n][3] - m1);
            s0 += e[n][0] + e[n][1];
            s1 += e[n][2] + e[n][3];
        }
        l0 = l0 * sc0 + s0;
        l1 = l1 * sc1 + s1;
#pragma unroll
        for (int n = 0; n < 8; n++) {
            o[n][0] *= sc0; o[n][1] *= sc0;
            o[n][2] *= sc1; o[n][3] *= sc1;
        }

        if (c < 3) { CP_WAIT(2); } else { CP_WAIT(0); }
        __syncthreads();
        uint32_t vbuf = sb + 32768 + (uint32_t)((c & 1) * 32768);

#pragma unroll
        for (int kk = 0; kk < 128; kk += 16) {
            int n2 = kk >> 3;
            uint32_t pa[4];
            pa[0] = h2u(e[n2][0],     e[n2][1]);
            pa[1] = h2u(e[n2][2],     e[n2][3]);
            pa[2] = h2u(e[n2 + 1][0], e[n2 + 1][1]);
            pa[3] = h2u(e[n2 + 1][2], e[n2 + 1][3]);
            int R = kk + a_row;
            int rx = R & 7;
            uint32_t vrow = vbuf + (uint32_t)(R * 128);
#pragma unroll
            for (int j = 0; j < 4; j++) {
                uint32_t bb0, bb1, bb2, bb3;
                ldmx4t(bb0, bb1, bb2, bb3,
                       vrow + (uint32_t)(((2 * j + a_g) ^ rx) << 4));
                uint32_t bA[2] = {bb0, bb1}, bB[2] = {bb2, bb3};
                mma_f16(o[2 * j],     pa, bA);
                mma_f16(o[2 * j + 1], pa, bB);
            }
        }
    }

    l0 += __shfl_xor_sync(0xffffffffu, l0, 1);
    l0 += __shfl_xor_sync(0xffffffffu, l0, 2);
    l1 += __shfl_xor_sync(0xffffffffu, l1, 1);
    l1 += __shfl_xor_sync(0xffffffffu, l1, 2);
    float inv0 = 1.f / l0;
    float inv1 = 1.f / l1;

    __half* Og = g_Oh + ((size_t)(b * LC + q0 + wm + g)) * DIMC + h * DHC;
    __half* Og2 = Og + 8 * DIMC;
#pragma unroll
    for (int n = 0; n < 8; n++) {
        *(__half2*)(Og + n * 8 + tg * 2)  = __floats2half2_rn(o[n][0] * inv0, o[n][1] * inv0);
        *(__half2*)(Og2 + n * 8 + tg * 2) = __floats2half2_rn(o[n][2] * inv1, o[n][3] * inv1);
    }
}

// ---------------------------------------------------------------------------
// Launch
// ---------------------------------------------------------------------------
extern "C" void kernel_launch(void* const* d_in, const int* in_sizes, int n_in,
                              void* d_out, int out_size) {
    const float* x   = (const float*)d_in[0];
    const float* ctx = (const float*)d_in[1];
    const float* Wq  = (const float*)d_in[2];
    const float* Wk  = (const float*)d_in[3];
    const float* Wv  = (const float*)d_in[4];
    const float* Wo  = (const float*)d_in[5];
    float* out = (float*)d_out;

    void *pXr, *pCr, *pWqT, *pWkvT, *pWoT, *pQ, *pK, *pV, *pOh;
    cudaGetSymbolAddress(&pXr, g_Xr);
    cudaGetSymbolAddress(&pCr, g_Cr);
    cudaGetSymbolAddress(&pWqT, g_WqT);
    cudaGetSymbolAddress(&pWkvT, g_WkvT);
    cudaGetSymbolAddress(&pWoT, g_WoT);
    cudaGetSymbolAddress(&pQ, g_Qh);
    cudaGetSymbolAddress(&pK, g_Kh);
    cudaGetSymbolAddress(&pV, g_Vh);
    cudaGetSymbolAddress(&pOh, g_Oh);

    __half* WkvT0 = (__half*)pWkvT;
    __half* WkvT1 = (__half*)pWkvT + (size_t)DIMC * DIMC;

    cudaFuncSetAttribute(mma_gemm_kernel, cudaFuncAttributeMaxDynamicSharedMemorySize, GSM_TOTAL);
    cudaFuncSetAttribute(attn_flash_kernel, cudaFuncAttributeMaxDynamicSharedMemorySize, AFL_SMEM);

    round_copy_h_kernel<<<(BC * LC * DIMC / 4 + 255) / 256, 256>>>(x,   (__half*)pXr, BC * LC * DIMC / 4);  // 0
    round_copy_h_kernel<<<(BC * RC * DIMC / 4 + 255) / 256, 256>>>(ctx, (__half*)pCr, BC * RC * DIMC / 4);  // 1
    dim3 tg3(DIMC / 32, DIMC / 32, 4);
    transpose_all_kernel<<<tg3, 256>>>(Wq, Wk, Wv, Wo,                                                       // 2
                                       (__half*)pWqT, WkvT0, WkvT1, (__half*)pWoT);

    // 3: fused K+V projection (fp16 out), N=2048 split at 1024
    mma_gemm_kernel<<<dim3(2 * DIMC / BNv, (BC * RC) / BMv), 256, GSM_TOTAL>>>(
        (const __half*)pCr, (const __half*)pWkvT, pK, pV, DIMC, 1);
    // 4: Q projection (fp16 out)
    mma_gemm_kernel<<<dim3(DIMC / BNv, (BC * LC) / BMv), 256, GSM_TOTAL>>>(
        (const __half*)pXr, (const __half*)pWqT, pQ, pQ, 1 << 30, 1);
    // 5: flash attention
    attn_flash_kernel<<<dim3(LC / 128, BC * HC), 256, AFL_SMEM>>>();
    // 6: output projection (fp32 out)
    mma_gemm_kernel<<<dim3(DIMC / BNv, (BC * LC) / BMv), 256, GSM_TOTAL>>>(
        (const __half*)pOh, (const __half*)pWoT, (void*)out, (void*)out, 1 << 30, 0);
}